// round 12
// baseline (speedup 1.0000x reference)
#include <cuda_runtime.h>
#include <math.h>

#define NANCH   25200
#define PSTRIDE 117
#define NBINS   8192
#define TOPK_K  1024
#define MAXDET  300
#define CONF_T  0.25f
#define IOU_T   0.45f
#define MAXWH   7680.0f
#define MASK_ELEMS 122880000ull   /* 300*640*640 */
#define SUP_BYTES (32 * TOPK_K * 4)   /* 128 KB */

/* ---------------- device scratch (static, allowed) ---------------- */
__device__ float    g_score[NANCH];
__device__ float    g_box[NANCH * 4];
__device__ int      g_cls[NANCH];
__device__ int      g_hist[NBINS];          /* zero-init; re-zeroed by select */

__device__ int      g_tidx[TOPK_K];
__device__ float    g_tscore[TOPK_K];
__device__ float    g_tbox[TOPK_K * 4];
__device__ float4   g_tnms[TOPK_K];
__device__ int      g_tcls[TOPK_K];
__device__ int      g_tvalid[TOPK_K];

__device__ unsigned g_supT[32 * TOPK_K];    /* word-major: g_supT[w*1024 + i] */

__device__ float    g_fb[MAXDET * 4];
__device__ float    g_fv[MAXDET];
__device__ int      g_rlo[MAXDET];
__device__ int      g_rhi[MAXDET];
__device__ float    g_coef[MAXDET * 32];
__device__ float    g_msig[MAXDET * 25600];

/* ---------------- 1: decode anchors (warp per anchor) ---------------- */
__global__ void decode_kernel(const float* __restrict__ pred) {
    int gw = (blockIdx.x * blockDim.x + threadIdx.x) >> 5;
    int lane = threadIdx.x & 31;
    if (gw >= NANCH) return;
    const float* p = pred + (size_t)gw * PSTRIDE;
    float v0 = p[lane];
    float v1 = p[32 + lane];
    float v2 = p[64 + lane];          /* 64+31=95 < 117, safe */
    float obj = __shfl_sync(0xffffffffu, v0, 4);

    /* per-lane candidates in ascending class order; strict > keeps first idx */
    float best = -1e30f; int bk = 1000;
    if (lane >= 5) { best = __fmul_rn(obj, v0); bk = lane - 5; }     /* k 0..26 */
    { float x = __fmul_rn(obj, v1); if (x > best) { best = x; bk = lane + 27; } } /* 27..58 */
    if (lane <= 20) { float x = __fmul_rn(obj, v2); if (x > best) { best = x; bk = lane + 59; } } /* 59..79 */
    #pragma unroll
    for (int off = 16; off; off >>= 1) {
        float ob = __shfl_down_sync(0xffffffffu, best, off);
        int ok = __shfl_down_sync(0xffffffffu, bk, off);
        if (ob > best || (ob == best && ok < bk)) { best = ob; bk = ok; }
    }
    float cx = __shfl_sync(0xffffffffu, v0, 0);
    float cy = __shfl_sync(0xffffffffu, v0, 1);
    float w  = __shfl_sync(0xffffffffu, v0, 2);
    float h  = __shfl_sync(0xffffffffu, v0, 3);
    if (lane == 0) {
        bool valid = (obj > CONF_T) && (best > CONF_T);
        float s = valid ? best : -1.0f;
        g_score[gw] = s;
        g_cls[gw] = bk;
        float hw = __fmul_rn(w, 0.5f), hh = __fmul_rn(h, 0.5f);
        g_box[gw * 4 + 0] = __fsub_rn(cx, hw);
        g_box[gw * 4 + 1] = __fsub_rn(cy, hh);
        g_box[gw * 4 + 2] = __fadd_rn(cx, hw);
        g_box[gw * 4 + 3] = __fadd_rn(cy, hh);
        if (valid) {
            int b = (int)((s - CONF_T) * (8192.0f / 0.75f));
            b = min(max(b, 0), NBINS - 1);
            atomicAdd(&g_hist[b], 1);
        }
    }
}

/* ---------------- 2: exact top-1024 (histogram threshold + bitonic) ------- */
__global__ void select_kernel() {
    __shared__ int s_scan[1024];
    __shared__ unsigned long long s_cand[4096];
    __shared__ int s_cnt;
    __shared__ int s_T;
    int t = threadIdx.x;

    int base = t * 8;
    int loc[8]; int sum = 0;
    #pragma unroll
    for (int k = 0; k < 8; k++) { loc[k] = g_hist[base + k]; sum += loc[k]; }
    #pragma unroll
    for (int k = 0; k < 8; k++) g_hist[base + k] = 0;   /* re-zero for next replay */
    s_scan[t] = sum;
    if (t == 0) { s_T = 0; s_cnt = 0; }
    __syncthreads();
    /* inclusive suffix scan of chunk sums */
    for (int off = 1; off < 1024; off <<= 1) {
        int add = (t + off < 1024) ? s_scan[t + off] : 0;
        __syncthreads();
        s_scan[t] += add;
        __syncthreads();
    }
    int suf_incl = s_scan[t];
    int suf_next = (t < 1023) ? s_scan[t + 1] : 0;
    if (suf_incl >= TOPK_K && suf_next < TOPK_K) {
        int acc = suf_next;
        int T = base;
        for (int b = 7; b >= 0; b--) {
            acc += loc[b];
            if (acc >= TOPK_K) { T = base + b; break; }
        }
        s_T = T;
    }
    __syncthreads();
    int T = s_T;
    /* compact candidates (bin >= T) */
    for (int i = t; i < NANCH; i += 1024) {
        float s = g_score[i];
        if (s > CONF_T) {
            int b = (int)((s - CONF_T) * (8192.0f / 0.75f));
            b = min(max(b, 0), NBINS - 1);
            if (b >= T) {
                int p = atomicAdd(&s_cnt, 1);
                if (p < 4096) {
                    unsigned k32 = __float_as_uint(s) ^ 0x80000000u;
                    s_cand[p] = ((unsigned long long)k32 << 32) |
                                (unsigned long long)(0xFFFFFFFFu - (unsigned)i);
                }
            }
        }
    }
    __syncthreads();
    int cnt = min(s_cnt, 4096);
    int M = (cnt <= 2048) ? 2048 : 4096;
    for (int p = t; p < M; p += 1024)
        if (p >= cnt) s_cand[p] = 0ull;
    __syncthreads();
    /* bitonic sort, descending, over M elements */
    for (unsigned k = 2; k <= (unsigned)M; k <<= 1) {
        for (unsigned j = k >> 1; j > 0; j >>= 1) {
            for (unsigned e = t; e < (unsigned)M; e += 1024) {
                unsigned q = e ^ j;
                if (q > e) {
                    unsigned long long a = s_cand[e], b = s_cand[q];
                    bool desc = ((e & k) == 0);
                    if (desc ? (a < b) : (a > b)) { s_cand[e] = b; s_cand[q] = a; }
                }
            }
            __syncthreads();
        }
    }
    /* emit top 1024 */
    unsigned long long key = s_cand[t];
    if (t < cnt && key != 0ull) {
        unsigned hi = (unsigned)(key >> 32);
        float s = __uint_as_float(hi ^ 0x80000000u);
        int idx = (int)(0xFFFFFFFFu - (unsigned)key);
        float b0 = g_box[idx * 4 + 0], b1 = g_box[idx * 4 + 1];
        float b2 = g_box[idx * 4 + 2], b3 = g_box[idx * 4 + 3];
        int c = g_cls[idx];
        float off = __fmul_rn((float)c, MAXWH);
        g_tidx[t] = idx; g_tscore[t] = s; g_tcls[t] = c; g_tvalid[t] = 1;
        g_tbox[t * 4 + 0] = b0; g_tbox[t * 4 + 1] = b1;
        g_tbox[t * 4 + 2] = b2; g_tbox[t * 4 + 3] = b3;
        g_tnms[t] = make_float4(__fadd_rn(b0, off), __fadd_rn(b1, off),
                                __fadd_rn(b2, off), __fadd_rn(b3, off));
    } else {
        g_tidx[t] = 0; g_tscore[t] = -1.0f; g_tcls[t] = 0; g_tvalid[t] = 0;
        g_tbox[t * 4 + 0] = 0.f; g_tbox[t * 4 + 1] = 0.f;
        g_tbox[t * 4 + 2] = 0.f; g_tbox[t * 4 + 3] = 0.f;
        g_tnms[t] = make_float4(0.f, 0.f, 0.f, 0.f);
    }
}

/* -------- 3: IoU suppression matrix, transposed (word-major) bits -------- */
__global__ void supmat_kernel() {
    __shared__ float4 s_nb[TOPK_K];
    int t = threadIdx.x;          /* 256 threads = 8 warps */
    int lane = t & 31, wid = t >> 5;
    for (int e = t; e < TOPK_K; e += 256) s_nb[e] = g_tnms[e];
    __syncthreads();
    int r = blockIdx.x * 8 + wid;
    float4 a = s_nb[r];
    float areaA = __fmul_rn(__fsub_rn(a.z, a.x), __fsub_rn(a.w, a.y));
    for (int wb = 0; wb < 32; wb++) {
        int j = wb * 32 + lane;
        float4 b = s_nb[j];
        float xx1 = fmaxf(a.x, b.x), yy1 = fmaxf(a.y, b.y);
        float xx2 = fminf(a.z, b.z), yy2 = fminf(a.w, b.w);
        float iw = fmaxf(__fsub_rn(xx2, xx1), 0.f);
        float ih = fmaxf(__fsub_rn(yy2, yy1), 0.f);
        float inter = __fmul_rn(iw, ih);
        float areaB = __fmul_rn(__fsub_rn(b.z, b.x), __fsub_rn(b.w, b.y));
        float denom = __fadd_rn(__fsub_rn(__fadd_rn(areaA, areaB), inter), 1e-7f);
        float iou = __fdiv_rn(inter, denom);
        unsigned m = __ballot_sync(0xffffffffu, iou > IOU_T);
        if (lane == 0) g_supT[wb * TOPK_K + r] = m;   /* word wb of row r */
    }
}

/* -- 4: greedy NMS — 8-warp scan w/ named barrier, 4 boxes per thread ----- */
__global__ void nms_kernel(const float* __restrict__ pred,
                           float* __restrict__ out) {
    extern __shared__ unsigned s_sup[];      /* 32*1024 words = 128 KB */
    __shared__ unsigned s_m[32];
    __shared__ unsigned s_keepA[32];
    __shared__ int s_wpref[32];
    __shared__ int s_i2[MAXDET];
    int t = threadIdx.x, lane = t & 31, wid = t >> 5;   /* 1024 threads */

    /* bulk-copy suppression matrix into smem (uint4, coalesced, all warps) */
    {
        const uint4* src = reinterpret_cast<const uint4*>(g_supT);
        uint4* dst = reinterpret_cast<uint4*>(s_sup);
        #pragma unroll
        for (int k = 0; k < 8; k++)
            dst[t + k * 1024] = src[t + k * 1024];
    }
    for (int r = t; r < MAXDET; r += 1024) s_i2[r] = -1;
    __syncthreads();

    if (t < 256) {
        /* thread t owns boxes t, t+256, t+512, t+768 (slot k=0..3) */
        unsigned validmask = 0u, suppmask = 0u;
        #pragma unroll
        for (int k = 0; k < 4; k++)
            validmask |= (g_tvalid[t + (k << 8)] != 0 ? 1u : 0u) << k;

        for (int b = 0; b < 32; b++) {
            int k = b >> 3;
            if (wid == (b & 7)) {
                /* this warp's slot-k boxes are exactly batch b's rows */
                bool base_ok = ((validmask >> k) & 1u) && !((suppmask >> k) & 1u);
                unsigned B = __ballot_sync(0xffffffffu, base_ok);
                unsigned Mi = s_sup[(b << 10) + t + (k << 8)];
                unsigned Mmask = lane ? (Mi & ((1u << lane) - 1u)) : 0u;
                s_m[lane] = Mmask;
                __syncwarp();
                if (lane == 0) {
                    unsigned K = 0u;
                    #pragma unroll
                    for (int j2 = 0; j2 < 32; j2++) {
                        if (((B >> j2) & 1u) && ((s_m[j2] & K) == 0u))
                            K |= (1u << j2);
                    }
                    s_keepA[b] = K;
                }
            }
            asm volatile("bar.sync 1, 256;" ::: "memory");
            /* incremental suppression update: 4 conflict-free LDS per thread */
            unsigned K = s_keepA[b];
            #pragma unroll
            for (int kk = 0; kk < 4; kk++)
                suppmask |= (((s_sup[(b << 10) + t + (kk << 8)] & K) != 0u)
                                 ? 1u : 0u) << kk;
        }
    }
    __syncthreads();
    if (t == 0) {
        int a = 0;
        for (int w = 0; w < 32; w++) { s_wpref[w] = a; a += __popc(s_keepA[w]); }
    }
    __syncthreads();
    {
        unsigned kwd = s_keepA[wid];
        if ((kwd >> lane) & 1u) {
            int rank = s_wpref[wid] + __popc(kwd & ((1u << lane) - 1u));
            if (rank < MAXDET) s_i2[rank] = t;
        }
    }
    __syncthreads();
    if (t < MAXDET) {
        int src = s_i2[t];
        float b0 = 0.f, b1 = 0.f, b2 = 0.f, b3 = 0.f, fs = 0.f;
        float fc = -1.0f, vflag = 0.f;
        int rlo = 1, rhi = 0;
        if (src >= 0) {
            b0 = g_tbox[src * 4 + 0]; b1 = g_tbox[src * 4 + 1];
            b2 = g_tbox[src * 4 + 2]; b3 = g_tbox[src * 4 + 3];
            fs = g_tscore[src]; fc = (float)g_tcls[src]; vflag = 1.0f;
            rlo = max(0, (int)floorf(0.25f * b1) - 1);
            rhi = min(159, (int)floorf(0.25f * b3) + 1);
        }
        size_t tb = 2ull * MASK_ELEMS;
        out[tb + t * 4 + 0] = b0; out[tb + t * 4 + 1] = b1;
        out[tb + t * 4 + 2] = b2; out[tb + t * 4 + 3] = b3;
        out[tb + 1200 + t] = fs;
        out[tb + 1500 + t] = fc;
        g_fb[t * 4 + 0] = b0; g_fb[t * 4 + 1] = b1;
        g_fb[t * 4 + 2] = b2; g_fb[t * 4 + 3] = b3;
        g_fv[t] = vflag;
        g_rlo[t] = rlo; g_rhi[t] = rhi;
        if (src >= 0) {
            const float* cp = pred + (size_t)g_tidx[src] * PSTRIDE + 85;
            #pragma unroll
            for (int k = 0; k < 32; k++) g_coef[t * 32 + k] = cp[k];
        } else {
            #pragma unroll
            for (int k = 0; k < 32; k++) g_coef[t * 32 + k] = 0.f;
        }
    }
}

/* ---------------- 5: crop-limited mask GEMM + sigmoid ---------------- */
__global__ void gemm_kernel(const float* __restrict__ protos) {
    int det = blockIdx.y;
    int r0 = blockIdx.x * 4;
    int rlo = g_rlo[det], rhi = g_rhi[det];
    if (r0 + 3 < rlo || r0 > rhi) return;
    __shared__ float cf[32];
    int t = threadIdx.x;                     /* 160 */
    if (t < 32) cf[t] = g_coef[det * 32 + t];
    __syncthreads();
    float a0 = 0.f, a1 = 0.f, a2 = 0.f, a3 = 0.f;
    const float* pp = protos + r0 * 160 + t;
    #pragma unroll
    for (int k = 0; k < 32; k++) {
        float c = cf[k];
        const float* q = pp + k * 25600;
        a0 = fmaf(c, q[0],   a0);
        a1 = fmaf(c, q[160], a1);
        a2 = fmaf(c, q[320], a2);
        a3 = fmaf(c, q[480], a3);
    }
    float* o = g_msig + (size_t)det * 25600 + r0 * 160 + t;
    o[0]   = 1.0f / (1.0f + expf(-a0));
    o[160] = 1.0f / (1.0f + expf(-a1));
    o[320] = 1.0f / (1.0f + expf(-a2));
    o[480] = 1.0f / (1.0f + expf(-a3));
}

/* ------- 6: bilinear 4x upsample + crop + threshold, sync-free core ------- */
__global__ void resize_kernel(float* __restrict__ out) {
    __shared__ float s[6][160];
    int det = blockIdx.y;
    int R = blockIdx.x * 16;       /* 16 output rows per block */
    int t = threadIdx.x;           /* 320 threads */
    int rh = t / 160;
    int c = t - rh * 160;

    float x1 = g_fb[det * 4 + 0], y1 = g_fb[det * 4 + 1];
    float x2 = g_fb[det * 4 + 2], y2 = g_fb[det * 4 + 3];
    float vmul = g_fv[det];
    bool active = (vmul > 0.5f) && ((float)(R + 15) >= y1) && ((float)R < y2);

    float4* of  = reinterpret_cast<float4*>(out) + (size_t)det * 102400ull;
    float4* obl = reinterpret_cast<float4*>(out + MASK_ELEMS) + (size_t)det * 102400ull;

    if (!active) {
        float4 z = make_float4(0.f, 0.f, 0.f, 0.f);
        #pragma unroll
        for (int yl = 0; yl < 8; yl++) {
            int yo = R + rh * 8 + yl;
            of[yo * 160 + c] = z;
            obl[yo * 160 + c] = z;
        }
        return;
    }

    int rbase = blockIdx.x * 4 - 1;
    const float* msrc = g_msig + (size_t)det * 25600;
    for (int e = t; e < 960; e += 320) {
        int rr = e / 160, cc = e - rr * 160;
        int r = min(max(rbase + rr, 0), 159);
        s[rr][cc] = msrc[r * 160 + cc];
    }
    __syncthreads();

    int cm1 = (c > 0) ? c - 1 : 0;
    int cp1 = (c < 159) ? c + 1 : 159;
    bool m0 = ((float)(4 * c)     >= x1) && ((float)(4 * c)     < x2);
    bool m1 = ((float)(4 * c + 1) >= x1) && ((float)(4 * c + 1) < x2);
    bool m2 = ((float)(4 * c + 2) >= x1) && ((float)(4 * c + 2) < x2);
    bool m3 = ((float)(4 * c + 3) >= x1) && ((float)(4 * c + 3) < x2);

    #pragma unroll
    for (int yl = 0; yl < 8; yl++) {
        int yo = R + rh * 8 + yl;
        float yf = (float)yo;
        bool rowok = (yf >= y1) && (yf < y2);
        float y = __fsub_rn(__fmul_rn(0.25f, yf), 0.375f);
        float y0f = floorf(y);
        int y0 = (int)y0f;
        float fy = __fsub_rn(y, y0f);
        float vm1, v0, vp1;
        if (y0 < 0) {
            int li = 0 - rbase;
            vm1 = s[li][cm1]; v0 = s[li][c]; vp1 = s[li][cp1];
        } else if (y0 > 158) {
            int li = 159 - rbase;
            vm1 = s[li][cm1]; v0 = s[li][c]; vp1 = s[li][cp1];
        } else {
            int l0 = y0 - rbase;
            float w1 = __fsub_rn(1.0f, fy);
            vm1 = __fadd_rn(__fmul_rn(s[l0][cm1], w1), __fmul_rn(s[l0 + 1][cm1], fy));
            v0  = __fadd_rn(__fmul_rn(s[l0][c],   w1), __fmul_rn(s[l0 + 1][c],   fy));
            vp1 = __fadd_rn(__fmul_rn(s[l0][cp1], w1), __fmul_rn(s[l0 + 1][cp1], fy));
        }
        float o0, o1, o2, o3;
        if (c == 0) { o0 = v0; o1 = v0; }
        else {
            o0 = __fadd_rn(__fmul_rn(vm1, 0.375f), __fmul_rn(v0, 0.625f));
            o1 = __fadd_rn(__fmul_rn(vm1, 0.125f), __fmul_rn(v0, 0.875f));
        }
        if (c == 159) { o2 = v0; o3 = v0; }
        else {
            o2 = __fadd_rn(__fmul_rn(v0, 0.875f), __fmul_rn(vp1, 0.125f));
            o3 = __fadd_rn(__fmul_rn(v0, 0.625f), __fmul_rn(vp1, 0.375f));
        }
        float4 fo;
        fo.x = (rowok && m0) ? o0 : 0.f;
        fo.y = (rowok && m1) ? o1 : 0.f;
        fo.z = (rowok && m2) ? o2 : 0.f;
        fo.w = (rowok && m3) ? o3 : 0.f;
        float4 bo;
        bo.x = fo.x > 0.5f ? 1.f : 0.f;
        bo.y = fo.y > 0.5f ? 1.f : 0.f;
        bo.z = fo.z > 0.5f ? 1.f : 0.f;
        bo.w = fo.w > 0.5f ? 1.f : 0.f;
        of[yo * 160 + c] = fo;
        obl[yo * 160 + c] = bo;
    }
}

/* ---------------- launch ---------------- */
extern "C" void kernel_launch(void* const* d_in, const int* in_sizes, int n_in,
                              void* d_out, int out_size) {
    const float* pred   = (const float*)d_in[0];
    const float* protos = (const float*)d_in[1];
    float* out = (float*)d_out;

    cudaFuncSetAttribute(nms_kernel,
                         cudaFuncAttributeMaxDynamicSharedMemorySize, SUP_BYTES);

    decode_kernel<<<(NANCH * 32 + 255) / 256, 256>>>(pred);
    select_kernel<<<1, 1024>>>();
    supmat_kernel<<<128, 256>>>();
    nms_kernel<<<1, 1024, SUP_BYTES>>>(pred, out);
    gemm_kernel<<<dim3(40, 300), 160>>>(protos);
    resize_kernel<<<dim3(40, 300), 320>>>(out);
}

// round 14
// speedup vs baseline: 1.2007x; 1.2007x over previous
#include <cuda_runtime.h>
#include <math.h>

#define NANCH   25200
#define PSTRIDE 117
#define NBINS   8192
#define TOPK_K  1024
#define MAXDET  300
#define CONF_T  0.25f
#define IOU_T   0.45f
#define MAXWH   7680.0f
#define MASK_ELEMS 122880000ull   /* 300*640*640 */
#define SUP_BYTES (32 * TOPK_K * 4)   /* 128 KB */

/* ---------------- device scratch (static, allowed) ---------------- */
__device__ float    g_score[NANCH];
__device__ float    g_box[NANCH * 4];
__device__ int      g_cls[NANCH];
__device__ int      g_hist[NBINS];          /* zero-init; re-zeroed by select */

__device__ int      g_tidx[TOPK_K];
__device__ float    g_tscore[TOPK_K];
__device__ float    g_tbox[TOPK_K * 4];
__device__ float4   g_tnms[TOPK_K];
__device__ int      g_tcls[TOPK_K];
__device__ int      g_tvalid[TOPK_K];

__device__ unsigned g_supT[32 * TOPK_K];    /* word-major: g_supT[w*1024 + i] */

__device__ float    g_fb[MAXDET * 4];
__device__ float    g_fv[MAXDET];
__device__ int      g_rlo[MAXDET];
__device__ int      g_rhi[MAXDET];
__device__ float    g_coef[MAXDET * 32];
__device__ float    g_msig[MAXDET * 25600];

/* ---------------- 1: decode anchors (warp per anchor) ---------------- */
__global__ void decode_kernel(const float* __restrict__ pred) {
    int gw = (blockIdx.x * blockDim.x + threadIdx.x) >> 5;
    int lane = threadIdx.x & 31;
    if (gw >= NANCH) return;
    const float* p = pred + (size_t)gw * PSTRIDE;
    float v0 = p[lane];
    float v1 = p[32 + lane];
    float v2 = p[64 + lane];          /* 64+31=95 < 117, safe */
    float obj = __shfl_sync(0xffffffffu, v0, 4);

    /* per-lane candidates in ascending class order; strict > keeps first idx */
    float best = -1e30f; int bk = 1000;
    if (lane >= 5) { best = __fmul_rn(obj, v0); bk = lane - 5; }     /* k 0..26 */
    { float x = __fmul_rn(obj, v1); if (x > best) { best = x; bk = lane + 27; } } /* 27..58 */
    if (lane <= 20) { float x = __fmul_rn(obj, v2); if (x > best) { best = x; bk = lane + 59; } } /* 59..79 */
    #pragma unroll
    for (int off = 16; off; off >>= 1) {
        float ob = __shfl_down_sync(0xffffffffu, best, off);
        int ok = __shfl_down_sync(0xffffffffu, bk, off);
        if (ob > best || (ob == best && ok < bk)) { best = ob; bk = ok; }
    }
    float cx = __shfl_sync(0xffffffffu, v0, 0);
    float cy = __shfl_sync(0xffffffffu, v0, 1);
    float w  = __shfl_sync(0xffffffffu, v0, 2);
    float h  = __shfl_sync(0xffffffffu, v0, 3);
    if (lane == 0) {
        bool valid = (obj > CONF_T) && (best > CONF_T);
        float s = valid ? best : -1.0f;
        g_score[gw] = s;
        g_cls[gw] = bk;
        float hw = __fmul_rn(w, 0.5f), hh = __fmul_rn(h, 0.5f);
        g_box[gw * 4 + 0] = __fsub_rn(cx, hw);
        g_box[gw * 4 + 1] = __fsub_rn(cy, hh);
        g_box[gw * 4 + 2] = __fadd_rn(cx, hw);
        g_box[gw * 4 + 3] = __fadd_rn(cy, hh);
        if (valid) {
            int b = (int)((s - CONF_T) * (8192.0f / 0.75f));
            b = min(max(b, 0), NBINS - 1);
            atomicAdd(&g_hist[b], 1);
        }
    }
}

/* ---------------- 2: exact top-1024 (histogram threshold + bitonic) ------- */
__global__ void select_kernel() {
    __shared__ int s_scan[1024];
    __shared__ unsigned long long s_cand[4096];
    __shared__ int s_cnt;
    __shared__ int s_T;
    int t = threadIdx.x;

    int base = t * 8;
    int loc[8]; int sum = 0;
    #pragma unroll
    for (int k = 0; k < 8; k++) { loc[k] = g_hist[base + k]; sum += loc[k]; }
    #pragma unroll
    for (int k = 0; k < 8; k++) g_hist[base + k] = 0;   /* re-zero for next replay */
    s_scan[t] = sum;
    if (t == 0) { s_T = 0; s_cnt = 0; }
    __syncthreads();
    /* inclusive suffix scan of chunk sums */
    for (int off = 1; off < 1024; off <<= 1) {
        int add = (t + off < 1024) ? s_scan[t + off] : 0;
        __syncthreads();
        s_scan[t] += add;
        __syncthreads();
    }
    int suf_incl = s_scan[t];
    int suf_next = (t < 1023) ? s_scan[t + 1] : 0;
    if (suf_incl >= TOPK_K && suf_next < TOPK_K) {
        int acc = suf_next;
        int T = base;
        for (int b = 7; b >= 0; b--) {
            acc += loc[b];
            if (acc >= TOPK_K) { T = base + b; break; }
        }
        s_T = T;
    }
    __syncthreads();
    int T = s_T;
    /* compact candidates (bin >= T) */
    for (int i = t; i < NANCH; i += 1024) {
        float s = g_score[i];
        if (s > CONF_T) {
            int b = (int)((s - CONF_T) * (8192.0f / 0.75f));
            b = min(max(b, 0), NBINS - 1);
            if (b >= T) {
                int p = atomicAdd(&s_cnt, 1);
                if (p < 4096) {
                    unsigned k32 = __float_as_uint(s) ^ 0x80000000u;
                    s_cand[p] = ((unsigned long long)k32 << 32) |
                                (unsigned long long)(0xFFFFFFFFu - (unsigned)i);
                }
            }
        }
    }
    __syncthreads();
    int cnt = min(s_cnt, 4096);
    int M = (cnt <= 2048) ? 2048 : 4096;
    for (int p = t; p < M; p += 1024)
        if (p >= cnt) s_cand[p] = 0ull;
    __syncthreads();
    /* bitonic sort, descending, over M elements */
    for (unsigned k = 2; k <= (unsigned)M; k <<= 1) {
        for (unsigned j = k >> 1; j > 0; j >>= 1) {
            for (unsigned e = t; e < (unsigned)M; e += 1024) {
                unsigned q = e ^ j;
                if (q > e) {
                    unsigned long long a = s_cand[e], b = s_cand[q];
                    bool desc = ((e & k) == 0);
                    if (desc ? (a < b) : (a > b)) { s_cand[e] = b; s_cand[q] = a; }
                }
            }
            __syncthreads();
        }
    }
    /* emit top 1024 */
    unsigned long long key = s_cand[t];
    if (t < cnt && key != 0ull) {
        unsigned hi = (unsigned)(key >> 32);
        float s = __uint_as_float(hi ^ 0x80000000u);
        int idx = (int)(0xFFFFFFFFu - (unsigned)key);
        float b0 = g_box[idx * 4 + 0], b1 = g_box[idx * 4 + 1];
        float b2 = g_box[idx * 4 + 2], b3 = g_box[idx * 4 + 3];
        int c = g_cls[idx];
        float off = __fmul_rn((float)c, MAXWH);
        g_tidx[t] = idx; g_tscore[t] = s; g_tcls[t] = c; g_tvalid[t] = 1;
        g_tbox[t * 4 + 0] = b0; g_tbox[t * 4 + 1] = b1;
        g_tbox[t * 4 + 2] = b2; g_tbox[t * 4 + 3] = b3;
        g_tnms[t] = make_float4(__fadd_rn(b0, off), __fadd_rn(b1, off),
                                __fadd_rn(b2, off), __fadd_rn(b3, off));
    } else {
        g_tidx[t] = 0; g_tscore[t] = -1.0f; g_tcls[t] = 0; g_tvalid[t] = 0;
        g_tbox[t * 4 + 0] = 0.f; g_tbox[t * 4 + 1] = 0.f;
        g_tbox[t * 4 + 2] = 0.f; g_tbox[t * 4 + 3] = 0.f;
        g_tnms[t] = make_float4(0.f, 0.f, 0.f, 0.f);
    }
}

/* --- 3: IoU suppression matrix — warp per row, L1-cached, no smem/bar ---- */
__global__ void supmat_kernel() {
    int lane = threadIdx.x & 31, wid = threadIdx.x >> 5;  /* 256 thr = 8 warps */
    int r = blockIdx.x * 8 + wid;
    float4 a = __ldg(&g_tnms[r]);
    float areaA = __fmul_rn(__fsub_rn(a.z, a.x), __fsub_rn(a.w, a.y));
    #pragma unroll 4
    for (int wb = 0; wb < 32; wb++) {
        float4 b = __ldg(&g_tnms[wb * 32 + lane]);
        float xx1 = fmaxf(a.x, b.x), yy1 = fmaxf(a.y, b.y);
        float xx2 = fminf(a.z, b.z), yy2 = fminf(a.w, b.w);
        float iw = fmaxf(__fsub_rn(xx2, xx1), 0.f);
        float ih = fmaxf(__fsub_rn(yy2, yy1), 0.f);
        float inter = __fmul_rn(iw, ih);
        float areaB = __fmul_rn(__fsub_rn(b.z, b.x), __fsub_rn(b.w, b.y));
        float denom = __fadd_rn(__fsub_rn(__fadd_rn(areaA, areaB), inter), 1e-7f);
        float iou = __fdiv_rn(inter, denom);
        unsigned m = __ballot_sync(0xffffffffu, iou > IOU_T);
        if (lane == 0) g_supT[wb * TOPK_K + r] = m;   /* word wb of row r */
    }
}

/* -- 4: greedy NMS — thread-per-box, incremental suppression, warp solve -- */
__global__ void nms_kernel(const float* __restrict__ pred,
                           float* __restrict__ out) {
    extern __shared__ unsigned s_sup[];      /* 32*1024 words = 128 KB */
    __shared__ unsigned s_m[32];
    __shared__ unsigned s_keepA[32];
    __shared__ int s_wpref[32];
    __shared__ int s_i2[MAXDET];
    int t = threadIdx.x, lane = t & 31, wid = t >> 5;   /* 1024 threads */

    /* bulk-copy suppression matrix into smem (uint4, coalesced) */
    {
        const uint4* src = reinterpret_cast<const uint4*>(g_supT);
        uint4* dst = reinterpret_cast<uint4*>(s_sup);
        #pragma unroll
        for (int k = 0; k < 8; k++)
            dst[t + k * 1024] = src[t + k * 1024];
    }
    bool valid = (g_tvalid[t] != 0);
    bool supp = false;                        /* suppressed by kept j < me */
    for (int r = t; r < MAXDET; r += 1024) s_i2[r] = -1;
    __syncthreads();

    for (int b = 0; b < 32; b++) {
        if (wid == b) {
            /* this warp owns batch b's 32 boxes */
            unsigned Mi = s_sup[(b << 10) + t];     /* word b of row t */
            bool base_ok = valid && !supp;
            unsigned B = __ballot_sync(0xffffffffu, base_ok);
            unsigned Mmask = lane ? (Mi & ((1u << lane) - 1u)) : 0u;
            s_m[lane] = Mmask;
            __syncwarp();
            if (lane == 0) {
                unsigned mm[32];
                #pragma unroll
                for (int j2 = 0; j2 < 32; j2++) mm[j2] = s_m[j2];
                unsigned K = 0u;
                #pragma unroll
                for (int j2 = 0; j2 < 32; j2++) {
                    if (((B >> j2) & 1u) && ((mm[j2] & K) == 0u))
                        K |= (1u << j2);
                }
                s_keepA[b] = K;
            }
        }
        __syncthreads();
        /* incremental suppression update: one conflict-free LDS per box */
        unsigned K = s_keepA[b];
        supp = supp || ((s_sup[(b << 10) + t] & K) != 0u);
    }
    __syncthreads();
    if (t == 0) {
        int a = 0;
        for (int w = 0; w < 32; w++) { s_wpref[w] = a; a += __popc(s_keepA[w]); }
    }
    __syncthreads();
    {
        unsigned kwd = s_keepA[wid];
        if ((kwd >> lane) & 1u) {
            int rank = s_wpref[wid] + __popc(kwd & ((1u << lane) - 1u));
            if (rank < MAXDET) s_i2[rank] = t;
        }
    }
    __syncthreads();
    if (t < MAXDET) {
        int src = s_i2[t];
        float b0 = 0.f, b1 = 0.f, b2 = 0.f, b3 = 0.f, fs = 0.f;
        float fc = -1.0f, vflag = 0.f;
        int rlo = 1, rhi = 0;
        if (src >= 0) {
            b0 = g_tbox[src * 4 + 0]; b1 = g_tbox[src * 4 + 1];
            b2 = g_tbox[src * 4 + 2]; b3 = g_tbox[src * 4 + 3];
            fs = g_tscore[src]; fc = (float)g_tcls[src]; vflag = 1.0f;
            rlo = max(0, (int)floorf(0.25f * b1) - 1);
            rhi = min(159, (int)floorf(0.25f * b3) + 1);
        }
        size_t tb = 2ull * MASK_ELEMS;
        out[tb + t * 4 + 0] = b0; out[tb + t * 4 + 1] = b1;
        out[tb + t * 4 + 2] = b2; out[tb + t * 4 + 3] = b3;
        out[tb + 1200 + t] = fs;
        out[tb + 1500 + t] = fc;
        g_fb[t * 4 + 0] = b0; g_fb[t * 4 + 1] = b1;
        g_fb[t * 4 + 2] = b2; g_fb[t * 4 + 3] = b3;
        g_fv[t] = vflag;
        g_rlo[t] = rlo; g_rhi[t] = rhi;
        if (src >= 0) {
            const float* cp = pred + (size_t)g_tidx[src] * PSTRIDE + 85;
            #pragma unroll
            for (int k = 0; k < 32; k++) g_coef[t * 32 + k] = cp[k];
        } else {
            #pragma unroll
            for (int k = 0; k < 32; k++) g_coef[t * 32 + k] = 0.f;
        }
    }
}

/* ---------------- 5: crop-limited mask GEMM + sigmoid ---------------- */
__global__ void gemm_kernel(const float* __restrict__ protos) {
    int det = blockIdx.y;
    int r0 = blockIdx.x * 4;
    int rlo = g_rlo[det], rhi = g_rhi[det];
    if (r0 + 3 < rlo || r0 > rhi) return;
    __shared__ float cf[32];
    int t = threadIdx.x;                     /* 160 */
    if (t < 32) cf[t] = g_coef[det * 32 + t];
    __syncthreads();
    float a0 = 0.f, a1 = 0.f, a2 = 0.f, a3 = 0.f;
    const float* pp = protos + r0 * 160 + t;
    #pragma unroll
    for (int k = 0; k < 32; k++) {
        float c = cf[k];
        const float* q = pp + k * 25600;
        a0 = fmaf(c, q[0],   a0);
        a1 = fmaf(c, q[160], a1);
        a2 = fmaf(c, q[320], a2);
        a3 = fmaf(c, q[480], a3);
    }
    float* o = g_msig + (size_t)det * 25600 + r0 * 160 + t;
    o[0]   = 1.0f / (1.0f + expf(-a0));
    o[160] = 1.0f / (1.0f + expf(-a1));
    o[320] = 1.0f / (1.0f + expf(-a2));
    o[480] = 1.0f / (1.0f + expf(-a3));
}

/* ------- 6: bilinear 4x upsample + crop + threshold, streaming stores ----- */
__global__ void resize_kernel(float* __restrict__ out) {
    __shared__ float s[6][160];
    int det = blockIdx.y;
    int R = blockIdx.x * 16;       /* 16 output rows per block */
    int t = threadIdx.x;           /* 320 threads */
    int rh = t / 160;
    int c = t - rh * 160;

    float x1 = g_fb[det * 4 + 0], y1 = g_fb[det * 4 + 1];
    float x2 = g_fb[det * 4 + 2], y2 = g_fb[det * 4 + 3];
    float vmul = g_fv[det];
    bool active = (vmul > 0.5f) && ((float)(R + 15) >= y1) && ((float)R < y2);

    float4* of  = reinterpret_cast<float4*>(out) + (size_t)det * 102400ull;
    float4* obl = reinterpret_cast<float4*>(out + MASK_ELEMS) + (size_t)det * 102400ull;

    if (!active) {
        float4 z = make_float4(0.f, 0.f, 0.f, 0.f);
        #pragma unroll
        for (int yl = 0; yl < 8; yl++) {
            int yo = R + rh * 8 + yl;
            __stcs(&of[yo * 160 + c], z);
            __stcs(&obl[yo * 160 + c], z);
        }
        return;
    }

    int rbase = blockIdx.x * 4 - 1;
    const float* msrc = g_msig + (size_t)det * 25600;
    for (int e = t; e < 960; e += 320) {
        int rr = e / 160, cc = e - rr * 160;
        int r = min(max(rbase + rr, 0), 159);
        s[rr][cc] = msrc[r * 160 + cc];
    }
    __syncthreads();

    int cm1 = (c > 0) ? c - 1 : 0;
    int cp1 = (c < 159) ? c + 1 : 159;
    bool m0 = ((float)(4 * c)     >= x1) && ((float)(4 * c)     < x2);
    bool m1 = ((float)(4 * c + 1) >= x1) && ((float)(4 * c + 1) < x2);
    bool m2 = ((float)(4 * c + 2) >= x1) && ((float)(4 * c + 2) < x2);
    bool m3 = ((float)(4 * c + 3) >= x1) && ((float)(4 * c + 3) < x2);

    #pragma unroll
    for (int yl = 0; yl < 8; yl++) {
        int yo = R + rh * 8 + yl;
        float yf = (float)yo;
        bool rowok = (yf >= y1) && (yf < y2);
        float y = __fsub_rn(__fmul_rn(0.25f, yf), 0.375f);
        float y0f = floorf(y);
        int y0 = (int)y0f;
        float fy = __fsub_rn(y, y0f);
        float vm1, v0, vp1;
        if (y0 < 0) {
            int li = 0 - rbase;
            vm1 = s[li][cm1]; v0 = s[li][c]; vp1 = s[li][cp1];
        } else if (y0 > 158) {
            int li = 159 - rbase;
            vm1 = s[li][cm1]; v0 = s[li][c]; vp1 = s[li][cp1];
        } else {
            int l0 = y0 - rbase;
            float w1 = __fsub_rn(1.0f, fy);
            vm1 = __fadd_rn(__fmul_rn(s[l0][cm1], w1), __fmul_rn(s[l0 + 1][cm1], fy));
            v0  = __fadd_rn(__fmul_rn(s[l0][c],   w1), __fmul_rn(s[l0 + 1][c],   fy));
            vp1 = __fadd_rn(__fmul_rn(s[l0][cp1], w1), __fmul_rn(s[l0 + 1][cp1], fy));
        }
        float o0, o1, o2, o3;
        if (c == 0) { o0 = v0; o1 = v0; }
        else {
            o0 = __fadd_rn(__fmul_rn(vm1, 0.375f), __fmul_rn(v0, 0.625f));
            o1 = __fadd_rn(__fmul_rn(vm1, 0.125f), __fmul_rn(v0, 0.875f));
        }
        if (c == 159) { o2 = v0; o3 = v0; }
        else {
            o2 = __fadd_rn(__fmul_rn(v0, 0.875f), __fmul_rn(vp1, 0.125f));
            o3 = __fadd_rn(__fmul_rn(v0, 0.625f), __fmul_rn(vp1, 0.375f));
        }
        float4 fo;
        fo.x = (rowok && m0) ? o0 : 0.f;
        fo.y = (rowok && m1) ? o1 : 0.f;
        fo.z = (rowok && m2) ? o2 : 0.f;
        fo.w = (rowok && m3) ? o3 : 0.f;
        float4 bo;
        bo.x = fo.x > 0.5f ? 1.f : 0.f;
        bo.y = fo.y > 0.5f ? 1.f : 0.f;
        bo.z = fo.z > 0.5f ? 1.f : 0.f;
        bo.w = fo.w > 0.5f ? 1.f : 0.f;
        __stcs(&of[yo * 160 + c], fo);
        __stcs(&obl[yo * 160 + c], bo);
    }
}

/* ---------------- launch ---------------- */
extern "C" void kernel_launch(void* const* d_in, const int* in_sizes, int n_in,
                              void* d_out, int out_size) {
    const float* pred   = (const float*)d_in[0];
    const float* protos = (const float*)d_in[1];
    float* out = (float*)d_out;

    cudaFuncSetAttribute(nms_kernel,
                         cudaFuncAttributeMaxDynamicSharedMemorySize, SUP_BYTES);

    decode_kernel<<<(NANCH * 32 + 255) / 256, 256>>>(pred);
    select_kernel<<<1, 1024>>>();
    supmat_kernel<<<128, 256>>>();
    nms_kernel<<<1, 1024, SUP_BYTES>>>(pred, out);
    gemm_kernel<<<dim3(40, 300), 160>>>(protos);
    resize_kernel<<<dim3(40, 300), 320>>>(out);
}

// round 17
// speedup vs baseline: 1.2431x; 1.0354x over previous
#include <cuda_runtime.h>
#include <math.h>

#define NANCH   25200
#define PSTRIDE 117
#define NBINS   8192
#define TOPK_K  1024
#define MAXDET  300
#define CONF_T  0.25f
#define IOU_T   0.45f
#define MAXWH   7680.0f
#define MASK_ELEMS 122880000ull   /* 300*640*640 */
#define SUP_BYTES (32 * TOPK_K * 4)   /* 128 KB */

/* zero-fill partition: 61.44M float4 = 3750 chunks of 16384 float4 (256 KB) */
#define FILL_CHUNK 16384
#define FILL_DECODE_N 400
#define FILL_SELECT_N 350
#define FILL_SUPMAT_N 600
#define FILL_NMS_N    1800
#define FILL_GEMM_N   600
#define FILL_DECODE_OFF 0
#define FILL_SELECT_OFF (FILL_DECODE_OFF + FILL_DECODE_N)   /* 400  */
#define FILL_SUPMAT_OFF (FILL_SELECT_OFF + FILL_SELECT_N)   /* 750  */
#define FILL_NMS_OFF    (FILL_SUPMAT_OFF + FILL_SUPMAT_N)   /* 1350 */
#define FILL_GEMM_OFF   (FILL_NMS_OFF + FILL_NMS_N)         /* 3150 */

__device__ __forceinline__ void fill_zero_chunk(float* out, int fid) {
    float4* dst = reinterpret_cast<float4*>(out) + (size_t)fid * FILL_CHUNK;
    float4 z = make_float4(0.f, 0.f, 0.f, 0.f);
    for (int i = threadIdx.x; i < FILL_CHUNK; i += blockDim.x)
        __stcs(&dst[i], z);
}

/* ---------------- device scratch (static, allowed) ---------------- */
__device__ float    g_score[NANCH];
__device__ float    g_box[NANCH * 4];
__device__ int      g_cls[NANCH];
__device__ int      g_hist[NBINS];          /* zero-init; re-zeroed by select */

__device__ int      g_tidx[TOPK_K];
__device__ float    g_tscore[TOPK_K];
__device__ float    g_tbox[TOPK_K * 4];
__device__ float4   g_tnms[TOPK_K];
__device__ int      g_tcls[TOPK_K];
__device__ int      g_tvalid[TOPK_K];

__device__ unsigned g_supT[32 * TOPK_K];    /* word-major: g_supT[w*1024 + i] */

__device__ float    g_fb[MAXDET * 4];
__device__ float    g_fv[MAXDET];
__device__ int      g_rlo[MAXDET];
__device__ int      g_rhi[MAXDET];
__device__ float    g_coef[MAXDET * 32];
__device__ float    g_msig[MAXDET * 25600];

/* ---------------- 1: decode anchors (warp per anchor) + fill ------------- */
__global__ void decode_kernel(const float* __restrict__ pred,
                              float* __restrict__ out) {
    if (blockIdx.x >= 3150) {     /* helper: zero-fill */
        fill_zero_chunk(out, (int)blockIdx.x - 3150 + FILL_DECODE_OFF);
        return;
    }
    int gw = (blockIdx.x * blockDim.x + threadIdx.x) >> 5;
    int lane = threadIdx.x & 31;
    const float* p = pred + (size_t)gw * PSTRIDE;
    float v0 = p[lane];
    float v1 = p[32 + lane];
    float v2 = p[64 + lane];          /* 64+31=95 < 117, safe */
    float obj = __shfl_sync(0xffffffffu, v0, 4);

    /* per-lane candidates in ascending class order; strict > keeps first idx */
    float best = -1e30f; int bk = 1000;
    if (lane >= 5) { best = __fmul_rn(obj, v0); bk = lane - 5; }     /* k 0..26 */
    { float x = __fmul_rn(obj, v1); if (x > best) { best = x; bk = lane + 27; } } /* 27..58 */
    if (lane <= 20) { float x = __fmul_rn(obj, v2); if (x > best) { best = x; bk = lane + 59; } } /* 59..79 */
    #pragma unroll
    for (int off = 16; off; off >>= 1) {
        float ob = __shfl_down_sync(0xffffffffu, best, off);
        int ok = __shfl_down_sync(0xffffffffu, bk, off);
        if (ob > best || (ob == best && ok < bk)) { best = ob; bk = ok; }
    }
    float cx = __shfl_sync(0xffffffffu, v0, 0);
    float cy = __shfl_sync(0xffffffffu, v0, 1);
    float w  = __shfl_sync(0xffffffffu, v0, 2);
    float h  = __shfl_sync(0xffffffffu, v0, 3);
    if (lane == 0) {
        bool valid = (obj > CONF_T) && (best > CONF_T);
        float s = valid ? best : -1.0f;
        g_score[gw] = s;
        g_cls[gw] = bk;
        float hw = __fmul_rn(w, 0.5f), hh = __fmul_rn(h, 0.5f);
        g_box[gw * 4 + 0] = __fsub_rn(cx, hw);
        g_box[gw * 4 + 1] = __fsub_rn(cy, hh);
        g_box[gw * 4 + 2] = __fadd_rn(cx, hw);
        g_box[gw * 4 + 3] = __fadd_rn(cy, hh);
        if (valid) {
            int b = (int)((s - CONF_T) * (8192.0f / 0.75f));
            b = min(max(b, 0), NBINS - 1);
            atomicAdd(&g_hist[b], 1);
        }
    }
}

/* ------- 2: exact top-1024 (histogram threshold + bitonic) + fill -------- */
__global__ void select_kernel(float* __restrict__ out) {
    if (blockIdx.x > 0) {
        fill_zero_chunk(out, (int)blockIdx.x - 1 + FILL_SELECT_OFF);
        return;
    }
    __shared__ int s_scan[1024];
    __shared__ unsigned long long s_cand[4096];
    __shared__ int s_cnt;
    __shared__ int s_T;
    int t = threadIdx.x;

    int base = t * 8;
    int loc[8]; int sum = 0;
    #pragma unroll
    for (int k = 0; k < 8; k++) { loc[k] = g_hist[base + k]; sum += loc[k]; }
    #pragma unroll
    for (int k = 0; k < 8; k++) g_hist[base + k] = 0;   /* re-zero for next replay */
    s_scan[t] = sum;
    if (t == 0) { s_T = 0; s_cnt = 0; }
    __syncthreads();
    /* inclusive suffix scan of chunk sums */
    for (int off = 1; off < 1024; off <<= 1) {
        int add = (t + off < 1024) ? s_scan[t + off] : 0;
        __syncthreads();
        s_scan[t] += add;
        __syncthreads();
    }
    int suf_incl = s_scan[t];
    int suf_next = (t < 1023) ? s_scan[t + 1] : 0;
    if (suf_incl >= TOPK_K && suf_next < TOPK_K) {
        int acc = suf_next;
        int T = base;
        for (int b = 7; b >= 0; b--) {
            acc += loc[b];
            if (acc >= TOPK_K) { T = base + b; break; }
        }
        s_T = T;
    }
    __syncthreads();
    int T = s_T;
    /* compact candidates (bin >= T) */
    for (int i = t; i < NANCH; i += 1024) {
        float s = g_score[i];
        if (s > CONF_T) {
            int b = (int)((s - CONF_T) * (8192.0f / 0.75f));
            b = min(max(b, 0), NBINS - 1);
            if (b >= T) {
                int p = atomicAdd(&s_cnt, 1);
                if (p < 4096) {
                    unsigned k32 = __float_as_uint(s) ^ 0x80000000u;
                    s_cand[p] = ((unsigned long long)k32 << 32) |
                                (unsigned long long)(0xFFFFFFFFu - (unsigned)i);
                }
            }
        }
    }
    __syncthreads();
    int cnt = min(s_cnt, 4096);
    int M = (cnt <= 2048) ? 2048 : 4096;
    for (int p = t; p < M; p += 1024)
        if (p >= cnt) s_cand[p] = 0ull;
    __syncthreads();
    /* bitonic sort, descending, over M elements */
    for (unsigned k = 2; k <= (unsigned)M; k <<= 1) {
        for (unsigned j = k >> 1; j > 0; j >>= 1) {
            for (unsigned e = t; e < (unsigned)M; e += 1024) {
                unsigned q = e ^ j;
                if (q > e) {
                    unsigned long long a = s_cand[e], b = s_cand[q];
                    bool desc = ((e & k) == 0);
                    if (desc ? (a < b) : (a > b)) { s_cand[e] = b; s_cand[q] = a; }
                }
            }
            __syncthreads();
        }
    }
    /* emit top 1024 */
    unsigned long long key = s_cand[t];
    if (t < cnt && key != 0ull) {
        unsigned hi = (unsigned)(key >> 32);
        float s = __uint_as_float(hi ^ 0x80000000u);
        int idx = (int)(0xFFFFFFFFu - (unsigned)key);
        float b0 = g_box[idx * 4 + 0], b1 = g_box[idx * 4 + 1];
        float b2 = g_box[idx * 4 + 2], b3 = g_box[idx * 4 + 3];
        int c = g_cls[idx];
        float off = __fmul_rn((float)c, MAXWH);
        g_tidx[t] = idx; g_tscore[t] = s; g_tcls[t] = c; g_tvalid[t] = 1;
        g_tbox[t * 4 + 0] = b0; g_tbox[t * 4 + 1] = b1;
        g_tbox[t * 4 + 2] = b2; g_tbox[t * 4 + 3] = b3;
        g_tnms[t] = make_float4(__fadd_rn(b0, off), __fadd_rn(b1, off),
                                __fadd_rn(b2, off), __fadd_rn(b3, off));
    } else {
        g_tidx[t] = 0; g_tscore[t] = -1.0f; g_tcls[t] = 0; g_tvalid[t] = 0;
        g_tbox[t * 4 + 0] = 0.f; g_tbox[t * 4 + 1] = 0.f;
        g_tbox[t * 4 + 2] = 0.f; g_tbox[t * 4 + 3] = 0.f;
        g_tnms[t] = make_float4(0.f, 0.f, 0.f, 0.f);
    }
}

/* --- 3: IoU suppression matrix — warp per row, L1-cached + fill ---------- */
__global__ void supmat_kernel(float* __restrict__ out) {
    if (blockIdx.x >= 128) {
        fill_zero_chunk(out, (int)blockIdx.x - 128 + FILL_SUPMAT_OFF);
        return;
    }
    int lane = threadIdx.x & 31, wid = threadIdx.x >> 5;  /* 256 thr = 8 warps */
    int r = blockIdx.x * 8 + wid;
    float4 a = __ldg(&g_tnms[r]);
    float areaA = __fmul_rn(__fsub_rn(a.z, a.x), __fsub_rn(a.w, a.y));
    #pragma unroll 4
    for (int wb = 0; wb < 32; wb++) {
        float4 b = __ldg(&g_tnms[wb * 32 + lane]);
        float xx1 = fmaxf(a.x, b.x), yy1 = fmaxf(a.y, b.y);
        float xx2 = fminf(a.z, b.z), yy2 = fminf(a.w, b.w);
        float iw = fmaxf(__fsub_rn(xx2, xx1), 0.f);
        float ih = fmaxf(__fsub_rn(yy2, yy1), 0.f);
        float inter = __fmul_rn(iw, ih);
        float areaB = __fmul_rn(__fsub_rn(b.z, b.x), __fsub_rn(b.w, b.y));
        float denom = __fadd_rn(__fsub_rn(__fadd_rn(areaA, areaB), inter), 1e-7f);
        float iou = __fdiv_rn(inter, denom);
        unsigned m = __ballot_sync(0xffffffffu, iou > IOU_T);
        if (lane == 0) g_supT[wb * TOPK_K + r] = m;   /* word wb of row r */
    }
}

/* -- 4: greedy NMS — thread-per-box, incremental suppression + fill ------- */
__global__ void nms_kernel(const float* __restrict__ pred,
                           float* __restrict__ out) {
    if (blockIdx.x > 0) {
        fill_zero_chunk(out, (int)blockIdx.x - 1 + FILL_NMS_OFF);
        return;
    }
    extern __shared__ unsigned s_sup[];      /* 32*1024 words = 128 KB */
    __shared__ unsigned s_m[32];
    __shared__ unsigned s_keepA[32];
    __shared__ int s_wpref[32];
    __shared__ int s_i2[MAXDET];
    int t = threadIdx.x, lane = t & 31, wid = t >> 5;   /* 1024 threads */

    /* bulk-copy suppression matrix into smem (uint4, coalesced) */
    {
        const uint4* src = reinterpret_cast<const uint4*>(g_supT);
        uint4* dst = reinterpret_cast<uint4*>(s_sup);
        #pragma unroll
        for (int k = 0; k < 8; k++)
            dst[t + k * 1024] = src[t + k * 1024];
    }
    bool valid = (g_tvalid[t] != 0);
    bool supp = false;                        /* suppressed by kept j < me */
    for (int r = t; r < MAXDET; r += 1024) s_i2[r] = -1;
    __syncthreads();

    for (int b = 0; b < 32; b++) {
        if (wid == b) {
            /* this warp owns batch b's 32 boxes */
            unsigned Mi = s_sup[(b << 10) + t];     /* word b of row t */
            bool base_ok = valid && !supp;
            unsigned B = __ballot_sync(0xffffffffu, base_ok);
            unsigned Mmask = lane ? (Mi & ((1u << lane) - 1u)) : 0u;
            s_m[lane] = Mmask;
            __syncwarp();
            if (lane == 0) {
                unsigned mm[32];
                #pragma unroll
                for (int j2 = 0; j2 < 32; j2++) mm[j2] = s_m[j2];
                unsigned K = 0u;
                #pragma unroll
                for (int j2 = 0; j2 < 32; j2++) {
                    if (((B >> j2) & 1u) && ((mm[j2] & K) == 0u))
                        K |= (1u << j2);
                }
                s_keepA[b] = K;
            }
        }
        __syncthreads();
        /* incremental suppression update: one conflict-free LDS per box */
        unsigned K = s_keepA[b];
        supp = supp || ((s_sup[(b << 10) + t] & K) != 0u);
    }
    __syncthreads();
    if (t == 0) {
        int a = 0;
        for (int w = 0; w < 32; w++) { s_wpref[w] = a; a += __popc(s_keepA[w]); }
    }
    __syncthreads();
    {
        unsigned kwd = s_keepA[wid];
        if ((kwd >> lane) & 1u) {
            int rank = s_wpref[wid] + __popc(kwd & ((1u << lane) - 1u));
            if (rank < MAXDET) s_i2[rank] = t;
        }
    }
    __syncthreads();
    if (t < MAXDET) {
        int src = s_i2[t];
        float b0 = 0.f, b1 = 0.f, b2 = 0.f, b3 = 0.f, fs = 0.f;
        float fc = -1.0f, vflag = 0.f;
        int rlo = 1, rhi = 0;
        if (src >= 0) {
            b0 = g_tbox[src * 4 + 0]; b1 = g_tbox[src * 4 + 1];
            b2 = g_tbox[src * 4 + 2]; b3 = g_tbox[src * 4 + 3];
            fs = g_tscore[src]; fc = (float)g_tcls[src]; vflag = 1.0f;
            rlo = max(0, (int)floorf(0.25f * b1) - 1);
            rhi = min(159, (int)floorf(0.25f * b3) + 1);
        }
        size_t tb = 2ull * MASK_ELEMS;
        out[tb + t * 4 + 0] = b0; out[tb + t * 4 + 1] = b1;
        out[tb + t * 4 + 2] = b2; out[tb + t * 4 + 3] = b3;
        out[tb + 1200 + t] = fs;
        out[tb + 1500 + t] = fc;
        g_fb[t * 4 + 0] = b0; g_fb[t * 4 + 1] = b1;
        g_fb[t * 4 + 2] = b2; g_fb[t * 4 + 3] = b3;
        g_fv[t] = vflag;
        g_rlo[t] = rlo; g_rhi[t] = rhi;
        if (src >= 0) {
            const float* cp = pred + (size_t)g_tidx[src] * PSTRIDE + 85;
            #pragma unroll
            for (int k = 0; k < 32; k++) g_coef[t * 32 + k] = cp[k];
        } else {
            #pragma unroll
            for (int k = 0; k < 32; k++) g_coef[t * 32 + k] = 0.f;
        }
    }
}

/* ---------------- 5: crop-limited mask GEMM + sigmoid + fill ------------- */
__global__ void gemm_kernel(const float* __restrict__ protos,
                            float* __restrict__ out) {
    if (blockIdx.x >= 40) {       /* helper: (bx-40)*300+by in [0,600) */
        fill_zero_chunk(out, ((int)blockIdx.x - 40) * 300 + (int)blockIdx.y
                             + FILL_GEMM_OFF);
        return;
    }
    int det = blockIdx.y;
    int r0 = blockIdx.x * 4;
    int rlo = g_rlo[det], rhi = g_rhi[det];
    if (r0 + 3 < rlo || r0 > rhi) return;
    __shared__ float cf[32];
    int t = threadIdx.x;                     /* 160 */
    if (t < 32) cf[t] = g_coef[det * 32 + t];
    __syncthreads();
    float a0 = 0.f, a1 = 0.f, a2 = 0.f, a3 = 0.f;
    const float* pp = protos + r0 * 160 + t;
    #pragma unroll
    for (int k = 0; k < 32; k++) {
        float c = cf[k];
        const float* q = pp + k * 25600;
        a0 = fmaf(c, q[0],   a0);
        a1 = fmaf(c, q[160], a1);
        a2 = fmaf(c, q[320], a2);
        a3 = fmaf(c, q[480], a3);
    }
    float* o = g_msig + (size_t)det * 25600 + r0 * 160 + t;
    o[0]   = 1.0f / (1.0f + expf(-a0));
    o[160] = 1.0f / (1.0f + expf(-a1));
    o[320] = 1.0f / (1.0f + expf(-a2));
    o[480] = 1.0f / (1.0f + expf(-a3));
}

/* ---- 6: bilinear 4x upsample + crop — active tiles, in-crop stores only -- */
__global__ void resize_kernel(float* __restrict__ out) {
    __shared__ float s[6][160];
    int det = blockIdx.y;
    int R = blockIdx.x * 16;       /* 16 output rows per block */
    int t = threadIdx.x;           /* 320 threads */
    int rh = t / 160;
    int c = t - rh * 160;

    float x1 = g_fb[det * 4 + 0], y1 = g_fb[det * 4 + 1];
    float x2 = g_fb[det * 4 + 2], y2 = g_fb[det * 4 + 3];
    float vmul = g_fv[det];
    bool active = (vmul > 0.5f) && ((float)(R + 15) >= y1) && ((float)R < y2);
    if (!active) return;           /* zeros already written by fill helpers */

    float4* of  = reinterpret_cast<float4*>(out) + (size_t)det * 102400ull;
    float4* obl = reinterpret_cast<float4*>(out + MASK_ELEMS) + (size_t)det * 102400ull;

    int rbase = blockIdx.x * 4 - 1;
    const float* msrc = g_msig + (size_t)det * 25600;
    for (int e = t; e < 960; e += 320) {
        int rr = e / 160, cc = e - rr * 160;
        int r = min(max(rbase + rr, 0), 159);
        s[rr][cc] = msrc[r * 160 + cc];
    }
    __syncthreads();

    int cm1 = (c > 0) ? c - 1 : 0;
    int cp1 = (c < 159) ? c + 1 : 159;
    bool m0 = ((float)(4 * c)     >= x1) && ((float)(4 * c)     < x2);
    bool m1 = ((float)(4 * c + 1) >= x1) && ((float)(4 * c + 1) < x2);
    bool m2 = ((float)(4 * c + 2) >= x1) && ((float)(4 * c + 2) < x2);
    bool m3 = ((float)(4 * c + 3) >= x1) && ((float)(4 * c + 3) < x2);
    bool anyx = m0 || m1 || m2 || m3;

    #pragma unroll
    for (int yl = 0; yl < 8; yl++) {
        int yo = R + rh * 8 + yl;
        float yf = (float)yo;
        bool rowok = (yf >= y1) && (yf < y2);
        if (!(rowok && anyx)) continue;   /* zeros pre-written */
        float y = __fsub_rn(__fmul_rn(0.25f, yf), 0.375f);
        float y0f = floorf(y);
        int y0 = (int)y0f;
        float fy = __fsub_rn(y, y0f);
        float vm1, v0, vp1;
        if (y0 < 0) {
            int li = 0 - rbase;
            vm1 = s[li][cm1]; v0 = s[li][c]; vp1 = s[li][cp1];
        } else if (y0 > 158) {
            int li = 159 - rbase;
            vm1 = s[li][cm1]; v0 = s[li][c]; vp1 = s[li][cp1];
        } else {
            int l0 = y0 - rbase;
            float w1 = __fsub_rn(1.0f, fy);
            vm1 = __fadd_rn(__fmul_rn(s[l0][cm1], w1), __fmul_rn(s[l0 + 1][cm1], fy));
            v0  = __fadd_rn(__fmul_rn(s[l0][c],   w1), __fmul_rn(s[l0 + 1][c],   fy));
            vp1 = __fadd_rn(__fmul_rn(s[l0][cp1], w1), __fmul_rn(s[l0 + 1][cp1], fy));
        }
        float o0, o1, o2, o3;
        if (c == 0) { o0 = v0; o1 = v0; }
        else {
            o0 = __fadd_rn(__fmul_rn(vm1, 0.375f), __fmul_rn(v0, 0.625f));
            o1 = __fadd_rn(__fmul_rn(vm1, 0.125f), __fmul_rn(v0, 0.875f));
        }
        if (c == 159) { o2 = v0; o3 = v0; }
        else {
            o2 = __fadd_rn(__fmul_rn(v0, 0.875f), __fmul_rn(vp1, 0.125f));
            o3 = __fadd_rn(__fmul_rn(v0, 0.625f), __fmul_rn(vp1, 0.375f));
        }
        float4 fo;
        fo.x = m0 ? o0 : 0.f;
        fo.y = m1 ? o1 : 0.f;
        fo.z = m2 ? o2 : 0.f;
        fo.w = m3 ? o3 : 0.f;
        float4 bo;
        bo.x = fo.x > 0.5f ? 1.f : 0.f;
        bo.y = fo.y > 0.5f ? 1.f : 0.f;
        bo.z = fo.z > 0.5f ? 1.f : 0.f;
        bo.w = fo.w > 0.5f ? 1.f : 0.f;
        __stcs(&of[yo * 160 + c], fo);
        __stcs(&obl[yo * 160 + c], bo);
    }
}

/* ---------------- launch ---------------- */
extern "C" void kernel_launch(void* const* d_in, const int* in_sizes, int n_in,
                              void* d_out, int out_size) {
    const float* pred   = (const float*)d_in[0];
    const float* protos = (const float*)d_in[1];
    float* out = (float*)d_out;

    cudaFuncSetAttribute(nms_kernel,
                         cudaFuncAttributeMaxDynamicSharedMemorySize, SUP_BYTES);

    decode_kernel<<<3150 + FILL_DECODE_N, 256>>>(pred, out);
    select_kernel<<<1 + FILL_SELECT_N, 1024>>>(out);
    supmat_kernel<<<128 + FILL_SUPMAT_N, 256>>>(out);
    nms_kernel<<<1 + FILL_NMS_N, 1024, SUP_BYTES>>>(pred, out);
    gemm_kernel<<<dim3(42, 300), 160>>>(protos, out);
    resize_kernel<<<dim3(40, 300), 320>>>(out);
}